// round 8
// baseline (speedup 1.0000x reference)
#include <cuda_runtime.h>
#include <cuda_fp16.h>
#include <cstdint>

#define NF 64
#define OUTF 12
#define N_MAX 50016
#define E_MAX 800000
#define NB_MAX 256          // scan blocks (N <= 65536)

// ------- scratch: __device__ globals only (allocation-free rule) -------
__device__ int     g_is64;                  // edge_index dtype flag
__device__ int     g_cnt   [N_MAX];         // in-degree count, then bucket cursor
__device__ float   g_degw  [N_MAX];         // weighted degree (incl. self loop)
__device__ int     g_rowptr[N_MAX + 1];
__device__ volatile int g_bflag[NB_MAX];    // lookback: 0=none 1=agg 2=incl
__device__ volatile int g_bvalA[NB_MAX];    // block aggregate
__device__ volatile int g_bvalI[NB_MAX];    // block inclusive prefix
__device__ int2    g_edge  [E_MAX];         // CSR slot: (src, weight-bits)
__device__ __half2 g_hs1   [N_MAX * 32];    // layer-1: dinv[i]*(x @ W1), fp16
__device__ __half2 g_hs2   [N_MAX * 32];    // layer-2: dinv[i]*(h @ W2), fp16

// ---------------------------------------------------------------------------
// init + dtype detect. Indices < 2^31, so int64 => every odd 32-bit word of
// the first 64 entries is zero (prob ~0 for random int32).
// ---------------------------------------------------------------------------
__global__ void k_init(const unsigned int* __restrict__ w, int n) {
    int i = blockIdx.x * blockDim.x + threadIdx.x;
    if (i < n) { g_cnt[i] = 0; g_degw[i] = 1.0f; }   // 1.0 = self loop
    if (i < NB_MAX) g_bflag[i] = 0;                  // reset lookback state
    if (blockIdx.x == 0 && threadIdx.x == 0) {
        int is64 = 1;
        for (int k = 0; k < 64; k++)
            if (w[2 * k + 1] != 0u) { is64 = 0; break; }
        g_is64 = is64;
    }
}

__device__ __forceinline__ int load_idx(const void* ei, long long pos) {
    if (g_is64) return (int)((const long long*)ei)[pos];
    return ((const int*)ei)[pos];
}

__global__ void k_count(const void* __restrict__ ei,
                        const float* __restrict__ ew, int E) {
    int e = blockIdx.x * blockDim.x + threadIdx.x;
    if (e < E) {
        int d = load_idx(ei, (long long)E + e);
        atomicAdd(&g_cnt[d], 1);
        atomicAdd(&g_degw[d], ew[e]);
    }
}

// ---------------------------------------------------------------------------
// Single-kernel exclusive scan of g_cnt -> g_rowptr (decoupled lookback).
// All blocks co-resident (256 thr, tiny smem) -> spin is deadlock-free.
// Resets g_cnt to 0 for the bucket pass. Last block writes rowptr[n].
// ---------------------------------------------------------------------------
__global__ void k_scan(int n, int nb) {
    __shared__ int wsum[8];
    __shared__ int sexcl;
    int tid = threadIdx.x, lane = tid & 31, wid = tid >> 5;
    int bid = blockIdx.x;
    int i = bid * 256 + tid;
    int v = (i < n) ? g_cnt[i] : 0;
    int x = v;
#pragma unroll
    for (int off = 1; off < 32; off <<= 1) {
        int y = __shfl_up_sync(0xffffffffu, x, off);
        if (lane >= off) x += y;
    }
    if (lane == 31) wsum[wid] = x;
    __syncthreads();
    if (tid == 0) {
        int we[8];
        int s = 0;
#pragma unroll
        for (int w = 0; w < 8; w++) { we[w] = s; s += wsum[w]; }
#pragma unroll
        for (int w = 0; w < 8; w++) wsum[w] = we[w];   // now warp-exclusive
        int agg = s;
        int excl = 0;
        if (bid == 0) {
            g_bvalI[0] = agg;
            __threadfence();
            g_bflag[0] = 2;
        } else {
            g_bvalA[bid] = agg;
            __threadfence();
            g_bflag[bid] = 1;
            for (int j = bid - 1; j >= 0; j--) {
                int f;
                while ((f = g_bflag[j]) == 0) { }
                if (f == 2) { excl += g_bvalI[j]; break; }
                excl += g_bvalA[j];
            }
            g_bvalI[bid] = excl + agg;
            __threadfence();
            g_bflag[bid] = 2;
        }
        sexcl = excl;
        if (bid == nb - 1) g_rowptr[n] = excl + agg;   // total edges
    }
    __syncthreads();
    if (i < n) {
        g_rowptr[i] = sexcl + wsum[wid] + (x - v);
        g_cnt[i] = 0;                                  // reset bucket cursors
    }
}

// ---------------------------------------------------------------------------
// Fused launch: blocks [0, ebN) bucket edges into CSR; blocks [ebN, ...)
// run the layer-1 GEMM. The two halves are independent and both memory-bound,
// so they overlap instead of serializing across launches.
// ---------------------------------------------------------------------------
__global__ void k_bkgm(const void* __restrict__ ei,
                       const float* __restrict__ ew,
                       const float* __restrict__ x,
                       const float* __restrict__ W,
                       int E, int n, int ebN) {
    __shared__ float Ws[NF * NF];
    __shared__ float xs[8][4][NF];

    if (blockIdx.x < ebN) {
        // ---- bucket ----
        int e = blockIdx.x * 256 + threadIdx.x;
        if (e < E) {
            int s = load_idx(ei, e);
            int d = load_idx(ei, (long long)E + e);
            int pos = g_rowptr[d] + atomicAdd(&g_cnt[d], 1);
            int2 p; p.x = s; p.y = __float_as_int(ew[e]);
            g_edge[pos] = p;
        }
        return;
    }

    // ---- gemm1: g_hs1[i][2l,2l+1] = rsqrt(degw[i]) * (x[i] @ W1)[2l,2l+1] ----
    int tid = threadIdx.x;
    for (int i = tid; i < NF * NF; i += blockDim.x) Ws[i] = W[i];
    __syncthreads();

    int warp = tid >> 5, lane = tid & 31;
    int row0 = ((blockIdx.x - ebN) * 8 + warp) * 4;
    if (row0 >= n) return;
    const float2* Ws2 = (const float2*)Ws;

#pragma unroll
    for (int r = 0; r < 4; r++) {
        int row = row0 + r;
        if (row < n) {
            xs[warp][r][lane]      = x[row * NF + lane];
            xs[warp][r][lane + 32] = x[row * NF + lane + 32];
        }
    }
    __syncwarp();

    float acc[4][2] = {};
#pragma unroll
    for (int k = 0; k < NF; k++) {
        float2 wv = Ws2[k * 32 + lane];     // W[k][2l], W[k][2l+1]
#pragma unroll
        for (int r = 0; r < 4; r++) {
            float xv = xs[warp][r][k];
            acc[r][0] = fmaf(xv, wv.x, acc[r][0]);
            acc[r][1] = fmaf(xv, wv.y, acc[r][1]);
        }
    }
#pragma unroll
    for (int r = 0; r < 4; r++) {
        int row = row0 + r;
        if (row < n) {
            float dv = rsqrtf(g_degw[row]);
            g_hs1[row * 32 + lane] =
                __floats2half2_rn(dv * acc[r][0], dv * acc[r][1]);
        }
    }
}

// ---------------------------------------------------------------------------
// Fused: gather layer 1 -> finalize -> GEMM layer 2 -> scale (fp16 out)
// Persistent grid; warp per node, lane owns features (2l, 2l+1).
// ---------------------------------------------------------------------------
__global__ void k_g1g2(const float* __restrict__ b1,
                       const float* __restrict__ W2, int n) {
    __shared__ float W2s[NF * NF];
    int tid = threadIdx.x;
    for (int i = tid; i < NF * NF; i += blockDim.x) W2s[i] = W2[i];
    __syncthreads();

    int lane = tid & 31;
    int gwarp = (blockIdx.x * blockDim.x + tid) >> 5;
    int nwarps = (gridDim.x * blockDim.x) >> 5;
    float bb0 = b1[2 * lane], bb1 = b1[2 * lane + 1];
    const float2* W2s2 = (const float2*)W2s;

    for (int row = gwarp; row < n; row += nwarps) {
        int beg = g_rowptr[row], end = g_rowptr[row + 1];
        float2 a = __half22float2(g_hs1[row * 32 + lane]);   // self loop (w=1)
        int e = beg;
        for (; e + 7 < end; e += 8) {
            int2 E0 = g_edge[e],   E1 = g_edge[e+1], E2 = g_edge[e+2], E3 = g_edge[e+3];
            int2 E4 = g_edge[e+4], E5 = g_edge[e+5], E6 = g_edge[e+6], E7 = g_edge[e+7];
            float2 v0 = __half22float2(g_hs1[E0.x * 32 + lane]);
            float2 v1 = __half22float2(g_hs1[E1.x * 32 + lane]);
            float2 v2 = __half22float2(g_hs1[E2.x * 32 + lane]);
            float2 v3 = __half22float2(g_hs1[E3.x * 32 + lane]);
            float2 v4 = __half22float2(g_hs1[E4.x * 32 + lane]);
            float2 v5 = __half22float2(g_hs1[E5.x * 32 + lane]);
            float2 v6 = __half22float2(g_hs1[E6.x * 32 + lane]);
            float2 v7 = __half22float2(g_hs1[E7.x * 32 + lane]);
            float w0 = __int_as_float(E0.y), w1 = __int_as_float(E1.y);
            float w2 = __int_as_float(E2.y), w3 = __int_as_float(E3.y);
            float w4 = __int_as_float(E4.y), w5 = __int_as_float(E5.y);
            float w6 = __int_as_float(E6.y), w7 = __int_as_float(E7.y);
            a.x = fmaf(w0, v0.x, a.x);  a.y = fmaf(w0, v0.y, a.y);
            a.x = fmaf(w1, v1.x, a.x);  a.y = fmaf(w1, v1.y, a.y);
            a.x = fmaf(w2, v2.x, a.x);  a.y = fmaf(w2, v2.y, a.y);
            a.x = fmaf(w3, v3.x, a.x);  a.y = fmaf(w3, v3.y, a.y);
            a.x = fmaf(w4, v4.x, a.x);  a.y = fmaf(w4, v4.y, a.y);
            a.x = fmaf(w5, v5.x, a.x);  a.y = fmaf(w5, v5.y, a.y);
            a.x = fmaf(w6, v6.x, a.x);  a.y = fmaf(w6, v6.y, a.y);
            a.x = fmaf(w7, v7.x, a.x);  a.y = fmaf(w7, v7.y, a.y);
        }
        for (; e < end; e++) {
            int2 E0 = g_edge[e];
            float2 v = __half22float2(g_hs1[E0.x * 32 + lane]);
            float w = __int_as_float(E0.y);
            a.x = fmaf(w, v.x, a.x);  a.y = fmaf(w, v.y, a.y);
        }
        float dv = rsqrtf(g_degw[row]);
        float h0 = fmaxf(fmaf(dv, a.x, bb0), 0.f);   // feature 2*lane
        float h1 = fmaxf(fmaf(dv, a.y, bb1), 0.f);   // feature 2*lane+1

        // hs2[row][2l,2l+1] = dv * sum_k h[k] * W2[k][2l,2l+1]
        float acc0 = 0.f, acc1 = 0.f;
#pragma unroll
        for (int kk = 0; kk < 32; kk++) {
            float hk0 = __shfl_sync(0xffffffffu, h0, kk);   // feature 2kk
            float hk1 = __shfl_sync(0xffffffffu, h1, kk);   // feature 2kk+1
            float2 wr0 = W2s2[(2 * kk) * 32 + lane];
            float2 wr1 = W2s2[(2 * kk + 1) * 32 + lane];
            acc0 = fmaf(hk0, wr0.x, acc0);  acc1 = fmaf(hk0, wr0.y, acc1);
            acc0 = fmaf(hk1, wr1.x, acc0);  acc1 = fmaf(hk1, wr1.y, acc1);
        }
        g_hs2[row * 32 + lane] = __floats2half2_rn(dv * acc0, dv * acc1);
    }
}

// ---------------------------------------------------------------------------
// Fused: gather layer 2 -> finalize -> FC head
// ---------------------------------------------------------------------------
__global__ void k_g2fc(const float* __restrict__ b2,
                       const float* __restrict__ Wfc,
                       const float* __restrict__ bfc,
                       float* __restrict__ out, int n) {
    int tid = threadIdx.x;
    int lane = tid & 31;
    int gwarp = (blockIdx.x * blockDim.x + tid) >> 5;
    int nwarps = (gridDim.x * blockDim.x) >> 5;

    float bb0 = b2[2 * lane], bb1 = b2[2 * lane + 1];
    float wf0[OUTF], wf1[OUTF];
#pragma unroll
    for (int j = 0; j < OUTF; j++) {
        wf0[j] = Wfc[(2 * lane) * OUTF + j];
        wf1[j] = Wfc[(2 * lane + 1) * OUTF + j];
    }
    float bfs = (lane < OUTF) ? bfc[lane] : 0.f;

    for (int row = gwarp; row < n; row += nwarps) {
        int beg = g_rowptr[row], end = g_rowptr[row + 1];
        float2 a = __half22float2(g_hs2[row * 32 + lane]);   // self loop
        int e = beg;
        for (; e + 7 < end; e += 8) {
            int2 E0 = g_edge[e],   E1 = g_edge[e+1], E2 = g_edge[e+2], E3 = g_edge[e+3];
            int2 E4 = g_edge[e+4], E5 = g_edge[e+5], E6 = g_edge[e+6], E7 = g_edge[e+7];
            float2 v0 = __half22float2(g_hs2[E0.x * 32 + lane]);
            float2 v1 = __half22float2(g_hs2[E1.x * 32 + lane]);
            float2 v2 = __half22float2(g_hs2[E2.x * 32 + lane]);
            float2 v3 = __half22float2(g_hs2[E3.x * 32 + lane]);
            float2 v4 = __half22float2(g_hs2[E4.x * 32 + lane]);
            float2 v5 = __half22float2(g_hs2[E5.x * 32 + lane]);
            float2 v6 = __half22float2(g_hs2[E6.x * 32 + lane]);
            float2 v7 = __half22float2(g_hs2[E7.x * 32 + lane]);
            float w0 = __int_as_float(E0.y), w1 = __int_as_float(E1.y);
            float w2 = __int_as_float(E2.y), w3 = __int_as_float(E3.y);
            float w4 = __int_as_float(E4.y), w5 = __int_as_float(E5.y);
            float w6 = __int_as_float(E6.y), w7 = __int_as_float(E7.y);
            a.x = fmaf(w0, v0.x, a.x);  a.y = fmaf(w0, v0.y, a.y);
            a.x = fmaf(w1, v1.x, a.x);  a.y = fmaf(w1, v1.y, a.y);
            a.x = fmaf(w2, v2.x, a.x);  a.y = fmaf(w2, v2.y, a.y);
            a.x = fmaf(w3, v3.x, a.x);  a.y = fmaf(w3, v3.y, a.y);
            a.x = fmaf(w4, v4.x, a.x);  a.y = fmaf(w4, v4.y, a.y);
            a.x = fmaf(w5, v5.x, a.x);  a.y = fmaf(w5, v5.y, a.y);
            a.x = fmaf(w6, v6.x, a.x);  a.y = fmaf(w6, v6.y, a.y);
            a.x = fmaf(w7, v7.x, a.x);  a.y = fmaf(w7, v7.y, a.y);
        }
        for (; e < end; e++) {
            int2 E0 = g_edge[e];
            float2 v = __half22float2(g_hs2[E0.x * 32 + lane]);
            float w = __int_as_float(E0.y);
            a.x = fmaf(w, v.x, a.x);  a.y = fmaf(w, v.y, a.y);
        }
        float dv = rsqrtf(g_degw[row]);
        float h0 = fmaxf(fmaf(dv, a.x, bb0), 0.f);
        float h1 = fmaxf(fmaf(dv, a.y, bb1), 0.f);

        float p[OUTF];
#pragma unroll
        for (int j = 0; j < OUTF; j++)
            p[j] = fmaf(h0, wf0[j], h1 * wf1[j]);
#pragma unroll
        for (int off = 16; off >= 1; off >>= 1)
#pragma unroll
            for (int j = 0; j < OUTF; j++)
                p[j] += __shfl_xor_sync(0xffffffffu, p[j], off);
        if (lane < OUTF)
            out[row * OUTF + lane] = p[lane] + bfs;  // all lanes hold full sums
    }
}

// ---------------------------------------------------------------------------
extern "C" void kernel_launch(void* const* d_in, const int* in_sizes, int n_in,
                              void* d_out, int out_size) {
    const float* x   = (const float*)d_in[0];
    const void*  ei  = d_in[1];                      // int32 OR int64 [2, E]
    const float* ea  = (const float*)d_in[2];        // [E, 1]
    const float* W1  = (const float*)d_in[3];
    const float* b1  = (const float*)d_in[4];
    const float* W2  = (const float*)d_in[5];
    const float* b2  = (const float*)d_in[6];
    const float* Wfc = (const float*)d_in[7];
    const float* bfc = (const float*)d_in[8];
    float* out = (float*)d_out;

    int N = in_sizes[0] / NF;
    int E = in_sizes[1] / 2;

    int nb = (N + 255) / 256;                        // scan blocks (<=256)
    int eb = (E + 255) / 256;
    int gb = (N + 31) / 32;                          // gemm1: 32 rows / block
    int pg = 148 * 8;                                // persistent gather grid
    int need = (N + 7) / 8;
    if (pg > need) pg = need;

    // CSR build (shared by both layers) + layer-1 GEMM overlapped with bucket
    k_init <<<nb, 256>>>((const unsigned int*)ei, N);
    k_count<<<eb, 256>>>(ei, ea, E);
    k_scan <<<nb, 256>>>(N, nb);
    k_bkgm <<<eb + gb, 256>>>(ei, ea, x, W1, E, N, eb);

    // Fused gather1+GEMM2, then fused gather2+FC
    k_g1g2<<<pg, 256>>>(b1, W2, N);
    k_g2fc<<<pg, 256>>>(b2, Wfc, bfc, out, N);
}

// round 10
// speedup vs baseline: 1.1321x; 1.1321x over previous
#include <cuda_runtime.h>
#include <cuda_fp16.h>
#include <cstdint>

#define NF 64
#define OUTF 12
#define N_MAX 50016
#define E_MAX 800000
#define NB_MAX 256          // scan blocks (N <= 65536)

// ------- scratch: __device__ globals only (allocation-free rule) -------
__device__ int     g_is64;                  // edge_index dtype flag
__device__ int     g_cnt   [N_MAX];         // in-degree count, then bucket cursor
__device__ float   g_degw  [N_MAX];         // weighted degree (incl. self loop)
__device__ int     g_rowptr[N_MAX + 1];
__device__ int     g_bsum  [NB_MAX];        // scan block partials
__device__ int2    g_edge  [E_MAX];         // CSR slot: (src, weight-bits)
__device__ __half2 g_hs1   [N_MAX * 32];    // layer-1: dinv[i]*(x @ W1), fp16
__device__ __half2 g_hs2   [N_MAX * 32];    // layer-2: dinv[i]*(h @ W2), fp16

// ---------------------------------------------------------------------------
// init + dtype detect. Indices < 2^31, so int64 => every odd 32-bit word of
// the first 64 entries is zero (prob ~0 for random int32).
// ---------------------------------------------------------------------------
__global__ void k_init(const unsigned int* __restrict__ w, int n) {
    int i = blockIdx.x * blockDim.x + threadIdx.x;
    if (i < n) { g_cnt[i] = 0; g_degw[i] = 1.0f; }   // 1.0 = self loop
    if (blockIdx.x == 0 && threadIdx.x == 0) {
        int is64 = 1;
        for (int k = 0; k < 64; k++)
            if (w[2 * k + 1] != 0u) { is64 = 0; break; }
        g_is64 = is64;
    }
}

__device__ __forceinline__ int load_idx(const void* ei, long long pos) {
    if (g_is64) return (int)((const long long*)ei)[pos];
    return ((const int*)ei)[pos];
}

// 4 edges per thread: batch independent loads first (MLP=8+), then atomics.
__global__ void k_count(const void* __restrict__ ei,
                        const float* __restrict__ ew, int E) {
    int e0 = (blockIdx.x * blockDim.x + threadIdx.x) * 4;
    if (e0 >= E) return;
    int m = E - e0; if (m > 4) m = 4;
    int d[4]; float w[4];
#pragma unroll
    for (int k = 0; k < 4; k++)
        if (k < m) d[k] = load_idx(ei, (long long)E + e0 + k);
#pragma unroll
    for (int k = 0; k < 4; k++)
        if (k < m) w[k] = ew[e0 + k];
#pragma unroll
    for (int k = 0; k < 4; k++)
        if (k < m) {
            atomicAdd(&g_cnt[d[k]], 1);
            atomicAdd(&g_degw[d[k]], w[k]);
        }
}

// ---- multi-block exclusive scan of g_cnt -> g_rowptr ----------------------
__global__ void k_scanA(int n) {
    __shared__ int wsum[8];
    __shared__ int wexcl[9];
    int tid = threadIdx.x, lane = tid & 31, wid = tid >> 5;
    int i = blockIdx.x * 256 + tid;
    int v = (i < n) ? g_cnt[i] : 0;
    int x = v;
#pragma unroll
    for (int off = 1; off < 32; off <<= 1) {
        int y = __shfl_up_sync(0xffffffffu, x, off);
        if (lane >= off) x += y;
    }
    if (lane == 31) wsum[wid] = x;
    __syncthreads();
    if (tid == 0) {
        int s = 0;
#pragma unroll
        for (int w = 0; w < 8; w++) { wexcl[w] = s; s += wsum[w]; }
        wexcl[8] = s;
    }
    __syncthreads();
    if (i < n) g_rowptr[i] = wexcl[wid] + x - v;     // block-local exclusive
    if (tid == 0) g_bsum[blockIdx.x] = wexcl[8];
}

__global__ void k_scanB(int nb, int n) {             // single block, nb<=256
    __shared__ int wsum[8];
    __shared__ int wexcl[9];
    int tid = threadIdx.x, lane = tid & 31, wid = tid >> 5;
    int v = (tid < nb) ? g_bsum[tid] : 0;
    int x = v;
#pragma unroll
    for (int off = 1; off < 32; off <<= 1) {
        int y = __shfl_up_sync(0xffffffffu, x, off);
        if (lane >= off) x += y;
    }
    if (lane == 31) wsum[wid] = x;
    __syncthreads();
    if (tid == 0) {
        int s = 0;
#pragma unroll
        for (int w = 0; w < 8; w++) { wexcl[w] = s; s += wsum[w]; }
        wexcl[8] = s;
        g_rowptr[n] = s;
    }
    __syncthreads();
    if (tid < nb) g_bsum[tid] = wexcl[wid] + x - v;  // exclusive block offsets
}

__global__ void k_scanC(int n) {
    int i = blockIdx.x * 256 + threadIdx.x;
    if (i < n) {
        g_rowptr[i] += g_bsum[blockIdx.x];
        g_cnt[i] = 0;                                // reset bucket cursors
    }
}

// 4 edges per thread, loads batched before the atomic/store chain.
__global__ void k_bucket(const void* __restrict__ ei,
                         const float* __restrict__ ew, int E) {
    int e0 = (blockIdx.x * blockDim.x + threadIdx.x) * 4;
    if (e0 >= E) return;
    int m = E - e0; if (m > 4) m = 4;
    int s[4], d[4]; float w[4];
#pragma unroll
    for (int k = 0; k < 4; k++)
        if (k < m) s[k] = load_idx(ei, e0 + k);
#pragma unroll
    for (int k = 0; k < 4; k++)
        if (k < m) d[k] = load_idx(ei, (long long)E + e0 + k);
#pragma unroll
    for (int k = 0; k < 4; k++)
        if (k < m) w[k] = ew[e0 + k];
#pragma unroll
    for (int k = 0; k < 4; k++)
        if (k < m) {
            int pos = g_rowptr[d[k]] + atomicAdd(&g_cnt[d[k]], 1);
            int2 p; p.x = s[k]; p.y = __float_as_int(w[k]);
            g_edge[pos] = p;
        }
}

// ---------------------------------------------------------------------------
// Layer-1 GEMM + scale:  g_hs1[i][2l,2l+1] = rsqrt(degw[i]) * (x[i] @ W1)[2l,2l+1]
// ---------------------------------------------------------------------------
__global__ void k_gemm1(const float* __restrict__ x,
                        const float* __restrict__ W, int n) {
    __shared__ float Ws[NF * NF];
    __shared__ float xs[8][4][NF];
    int tid = threadIdx.x;
    for (int i = tid; i < NF * NF; i += blockDim.x) Ws[i] = W[i];
    __syncthreads();

    int warp = tid >> 5, lane = tid & 31;
    int row0 = (blockIdx.x * 8 + warp) * 4;
    if (row0 >= n) return;
    const float2* Ws2 = (const float2*)Ws;

#pragma unroll
    for (int r = 0; r < 4; r++) {
        int row = row0 + r;
        if (row < n) {
            xs[warp][r][lane]      = x[row * NF + lane];
            xs[warp][r][lane + 32] = x[row * NF + lane + 32];
        }
    }
    __syncwarp();

    float acc[4][2] = {};
#pragma unroll
    for (int k = 0; k < NF; k++) {
        float2 wv = Ws2[k * 32 + lane];     // W[k][2l], W[k][2l+1]
#pragma unroll
        for (int r = 0; r < 4; r++) {
            float xv = xs[warp][r][k];
            acc[r][0] = fmaf(xv, wv.x, acc[r][0]);
            acc[r][1] = fmaf(xv, wv.y, acc[r][1]);
        }
    }
#pragma unroll
    for (int r = 0; r < 4; r++) {
        int row = row0 + r;
        if (row < n) {
            float dv = rsqrtf(g_degw[row]);
            g_hs1[row * 32 + lane] =
                __floats2half2_rn(dv * acc[r][0], dv * acc[r][1]);
        }
    }
}

// ---------------------------------------------------------------------------
// Fused: gather layer 1 -> finalize -> GEMM layer 2 -> scale (fp16 out)
// Persistent grid; warp per node, lane owns features (2l, 2l+1).
// ---------------------------------------------------------------------------
__global__ void k_g1g2(const float* __restrict__ b1,
                       const float* __restrict__ W2, int n) {
    __shared__ float W2s[NF * NF];
    int tid = threadIdx.x;
    for (int i = tid; i < NF * NF; i += blockDim.x) W2s[i] = W2[i];
    __syncthreads();

    int lane = tid & 31;
    int gwarp = (blockIdx.x * blockDim.x + tid) >> 5;
    int nwarps = (gridDim.x * blockDim.x) >> 5;
    float bb0 = b1[2 * lane], bb1 = b1[2 * lane + 1];
    const float2* W2s2 = (const float2*)W2s;

    for (int row = gwarp; row < n; row += nwarps) {
        int beg = g_rowptr[row], end = g_rowptr[row + 1];
        float2 a = __half22float2(g_hs1[row * 32 + lane]);   // self loop (w=1)
        int e = beg;
        for (; e + 7 < end; e += 8) {
            int2 E0 = g_edge[e],   E1 = g_edge[e+1], E2 = g_edge[e+2], E3 = g_edge[e+3];
            int2 E4 = g_edge[e+4], E5 = g_edge[e+5], E6 = g_edge[e+6], E7 = g_edge[e+7];
            float2 v0 = __half22float2(g_hs1[E0.x * 32 + lane]);
            float2 v1 = __half22float2(g_hs1[E1.x * 32 + lane]);
            float2 v2 = __half22float2(g_hs1[E2.x * 32 + lane]);
            float2 v3 = __half22float2(g_hs1[E3.x * 32 + lane]);
            float2 v4 = __half22float2(g_hs1[E4.x * 32 + lane]);
            float2 v5 = __half22float2(g_hs1[E5.x * 32 + lane]);
            float2 v6 = __half22float2(g_hs1[E6.x * 32 + lane]);
            float2 v7 = __half22float2(g_hs1[E7.x * 32 + lane]);
            float w0 = __int_as_float(E0.y), w1 = __int_as_float(E1.y);
            float w2 = __int_as_float(E2.y), w3 = __int_as_float(E3.y);
            float w4 = __int_as_float(E4.y), w5 = __int_as_float(E5.y);
            float w6 = __int_as_float(E6.y), w7 = __int_as_float(E7.y);
            a.x = fmaf(w0, v0.x, a.x);  a.y = fmaf(w0, v0.y, a.y);
            a.x = fmaf(w1, v1.x, a.x);  a.y = fmaf(w1, v1.y, a.y);
            a.x = fmaf(w2, v2.x, a.x);  a.y = fmaf(w2, v2.y, a.y);
            a.x = fmaf(w3, v3.x, a.x);  a.y = fmaf(w3, v3.y, a.y);
            a.x = fmaf(w4, v4.x, a.x);  a.y = fmaf(w4, v4.y, a.y);
            a.x = fmaf(w5, v5.x, a.x);  a.y = fmaf(w5, v5.y, a.y);
            a.x = fmaf(w6, v6.x, a.x);  a.y = fmaf(w6, v6.y, a.y);
            a.x = fmaf(w7, v7.x, a.x);  a.y = fmaf(w7, v7.y, a.y);
        }
        for (; e < end; e++) {
            int2 E0 = g_edge[e];
            float2 v = __half22float2(g_hs1[E0.x * 32 + lane]);
            float w = __int_as_float(E0.y);
            a.x = fmaf(w, v.x, a.x);  a.y = fmaf(w, v.y, a.y);
        }
        float dv = rsqrtf(g_degw[row]);
        float h0 = fmaxf(fmaf(dv, a.x, bb0), 0.f);   // feature 2*lane
        float h1 = fmaxf(fmaf(dv, a.y, bb1), 0.f);   // feature 2*lane+1

        // hs2[row][2l,2l+1] = dv * sum_k h[k] * W2[k][2l,2l+1]
        float acc0 = 0.f, acc1 = 0.f;
#pragma unroll
        for (int kk = 0; kk < 32; kk++) {
            float hk0 = __shfl_sync(0xffffffffu, h0, kk);   // feature 2kk
            float hk1 = __shfl_sync(0xffffffffu, h1, kk);   // feature 2kk+1
            float2 wr0 = W2s2[(2 * kk) * 32 + lane];
            float2 wr1 = W2s2[(2 * kk + 1) * 32 + lane];
            acc0 = fmaf(hk0, wr0.x, acc0);  acc1 = fmaf(hk0, wr0.y, acc1);
            acc0 = fmaf(hk1, wr1.x, acc0);  acc1 = fmaf(hk1, wr1.y, acc1);
        }
        g_hs2[row * 32 + lane] = __floats2half2_rn(dv * acc0, dv * acc1);
    }
}

// ---------------------------------------------------------------------------
// Fused: gather layer 2 -> finalize -> FC head
// ---------------------------------------------------------------------------
__global__ void k_g2fc(const float* __restrict__ b2,
                       const float* __restrict__ Wfc,
                       const float* __restrict__ bfc,
                       float* __restrict__ out, int n) {
    int tid = threadIdx.x;
    int lane = tid & 31;
    int gwarp = (blockIdx.x * blockDim.x + tid) >> 5;
    int nwarps = (gridDim.x * blockDim.x) >> 5;

    float bb0 = b2[2 * lane], bb1 = b2[2 * lane + 1];
    float wf0[OUTF], wf1[OUTF];
#pragma unroll
    for (int j = 0; j < OUTF; j++) {
        wf0[j] = Wfc[(2 * lane) * OUTF + j];
        wf1[j] = Wfc[(2 * lane + 1) * OUTF + j];
    }
    float bfs = (lane < OUTF) ? bfc[lane] : 0.f;

    for (int row = gwarp; row < n; row += nwarps) {
        int beg = g_rowptr[row], end = g_rowptr[row + 1];
        float2 a = __half22float2(g_hs2[row * 32 + lane]);   // self loop
        int e = beg;
        for (; e + 7 < end; e += 8) {
            int2 E0 = g_edge[e],   E1 = g_edge[e+1], E2 = g_edge[e+2], E3 = g_edge[e+3];
            int2 E4 = g_edge[e+4], E5 = g_edge[e+5], E6 = g_edge[e+6], E7 = g_edge[e+7];
            float2 v0 = __half22float2(g_hs2[E0.x * 32 + lane]);
            float2 v1 = __half22float2(g_hs2[E1.x * 32 + lane]);
            float2 v2 = __half22float2(g_hs2[E2.x * 32 + lane]);
            float2 v3 = __half22float2(g_hs2[E3.x * 32 + lane]);
            float2 v4 = __half22float2(g_hs2[E4.x * 32 + lane]);
            float2 v5 = __half22float2(g_hs2[E5.x * 32 + lane]);
            float2 v6 = __half22float2(g_hs2[E6.x * 32 + lane]);
            float2 v7 = __half22float2(g_hs2[E7.x * 32 + lane]);
            float w0 = __int_as_float(E0.y), w1 = __int_as_float(E1.y);
            float w2 = __int_as_float(E2.y), w3 = __int_as_float(E3.y);
            float w4 = __int_as_float(E4.y), w5 = __int_as_float(E5.y);
            float w6 = __int_as_float(E6.y), w7 = __int_as_float(E7.y);
            a.x = fmaf(w0, v0.x, a.x);  a.y = fmaf(w0, v0.y, a.y);
            a.x = fmaf(w1, v1.x, a.x);  a.y = fmaf(w1, v1.y, a.y);
            a.x = fmaf(w2, v2.x, a.x);  a.y = fmaf(w2, v2.y, a.y);
            a.x = fmaf(w3, v3.x, a.x);  a.y = fmaf(w3, v3.y, a.y);
            a.x = fmaf(w4, v4.x, a.x);  a.y = fmaf(w4, v4.y, a.y);
            a.x = fmaf(w5, v5.x, a.x);  a.y = fmaf(w5, v5.y, a.y);
            a.x = fmaf(w6, v6.x, a.x);  a.y = fmaf(w6, v6.y, a.y);
            a.x = fmaf(w7, v7.x, a.x);  a.y = fmaf(w7, v7.y, a.y);
        }
        for (; e < end; e++) {
            int2 E0 = g_edge[e];
            float2 v = __half22float2(g_hs2[E0.x * 32 + lane]);
            float w = __int_as_float(E0.y);
            a.x = fmaf(w, v.x, a.x);  a.y = fmaf(w, v.y, a.y);
        }
        float dv = rsqrtf(g_degw[row]);
        float h0 = fmaxf(fmaf(dv, a.x, bb0), 0.f);
        float h1 = fmaxf(fmaf(dv, a.y, bb1), 0.f);

        float p[OUTF];
#pragma unroll
        for (int j = 0; j < OUTF; j++)
            p[j] = fmaf(h0, wf0[j], h1 * wf1[j]);
#pragma unroll
        for (int off = 16; off >= 1; off >>= 1)
#pragma unroll
            for (int j = 0; j < OUTF; j++)
                p[j] += __shfl_xor_sync(0xffffffffu, p[j], off);
        if (lane < OUTF)
            out[row * OUTF + lane] = p[lane] + bfs;  // all lanes hold full sums
    }
}

// ---------------------------------------------------------------------------
extern "C" void kernel_launch(void* const* d_in, const int* in_sizes, int n_in,
                              void* d_out, int out_size) {
    const float* x   = (const float*)d_in[0];
    const void*  ei  = d_in[1];                      // int32 OR int64 [2, E]
    const float* ea  = (const float*)d_in[2];        // [E, 1]
    const float* W1  = (const float*)d_in[3];
    const float* b1  = (const float*)d_in[4];
    const float* W2  = (const float*)d_in[5];
    const float* b2  = (const float*)d_in[6];
    const float* Wfc = (const float*)d_in[7];
    const float* bfc = (const float*)d_in[8];
    float* out = (float*)d_out;

    int N = in_sizes[0] / NF;
    int E = in_sizes[1] / 2;

    int nb  = (N + 255) / 256;                       // scan blocks (<=256)
    int eb4 = (E + 1023) / 1024;                     // 4 edges per thread
    int gb  = (N + 31) / 32;                         // gemm1: 32 rows / block
    int pg  = 148 * 8;                               // persistent gather grid
    int need = (N + 7) / 8;
    if (pg > need) pg = need;

    // CSR build (shared by both layers)
    k_init  <<<nb, 256>>>((const unsigned int*)ei, N);
    k_count <<<eb4, 256>>>(ei, ea, E);
    k_scanA <<<nb, 256>>>(N);
    k_scanB <<<1, 256>>>(nb, N);
    k_scanC <<<nb, 256>>>(N);
    k_bucket<<<eb4, 256>>>(ei, ea, E);

    // Layer 1 GEMM, then fused gather1+GEMM2, then fused gather2+FC
    k_gemm1<<<gb, 256>>>(x, W1, N);
    k_g1g2 <<<pg, 256>>>(b1, W2, N);
    k_g2fc <<<pg, 256>>>(b2, Wfc, bfc, out, N);
}

// round 11
// speedup vs baseline: 1.1824x; 1.0445x over previous
#include <cuda_runtime.h>
#include <cuda_fp16.h>
#include <cstdint>

#define NF 64
#define OUTF 12
#define N_MAX 50016
#define E_MAX 800000
#define NB_MAX 256          // scan blocks (N <= 65536)

// ------- scratch: __device__ globals only (allocation-free rule) -------
__device__ int     g_is64;                  // edge_index dtype flag
__device__ int     g_cnt   [N_MAX];         // in-degree count, then bucket cursor
__device__ float   g_degw  [N_MAX];         // weighted degree (incl. self loop)
__device__ int     g_rowptr[N_MAX + 1];
__device__ int     g_bsum  [NB_MAX];        // scan block partials
__device__ int2    g_edge  [E_MAX];         // CSR slot: (src, weight-bits)
__device__ __half2 g_hs1   [N_MAX * 32];    // layer-1: dinv[i]*(x @ W1), fp16
__device__ __half2 g_hs2   [N_MAX * 32];    // layer-2: dinv[i]*(h @ W2), fp16

// ---------------------------------------------------------------------------
// init + dtype detect. Indices < 2^31, so int64 => every odd 32-bit word of
// the first 64 entries is zero (prob ~0 for random int32).
// ---------------------------------------------------------------------------
__global__ void k_init(const unsigned int* __restrict__ w, int n) {
    int i = blockIdx.x * blockDim.x + threadIdx.x;
    if (i < n) { g_cnt[i] = 0; g_degw[i] = 1.0f; }   // 1.0 = self loop
    if (blockIdx.x == 0 && threadIdx.x == 0) {
        int is64 = 1;
        for (int k = 0; k < 64; k++)
            if (w[2 * k + 1] != 0u) { is64 = 0; break; }
        g_is64 = is64;
    }
}

__device__ __forceinline__ int load_idx(const void* ei, long long pos) {
    if (g_is64) return (int)((const long long*)ei)[pos];
    return ((const int*)ei)[pos];
}

__global__ void k_count(const void* __restrict__ ei,
                        const float* __restrict__ ew, int E) {
    int e = blockIdx.x * blockDim.x + threadIdx.x;
    if (e < E) {
        int d = load_idx(ei, (long long)E + e);
        atomicAdd(&g_cnt[d], 1);
        atomicAdd(&g_degw[d], ew[e]);
    }
}

// ---- scan step A: block-local exclusive scan + block aggregates -----------
__global__ void k_scanA(int n) {
    __shared__ int wsum[8];
    __shared__ int wexcl[9];
    int tid = threadIdx.x, lane = tid & 31, wid = tid >> 5;
    int i = blockIdx.x * 256 + tid;
    int v = (i < n) ? g_cnt[i] : 0;
    int x = v;
#pragma unroll
    for (int off = 1; off < 32; off <<= 1) {
        int y = __shfl_up_sync(0xffffffffu, x, off);
        if (lane >= off) x += y;
    }
    if (lane == 31) wsum[wid] = x;
    __syncthreads();
    if (tid == 0) {
        int s = 0;
#pragma unroll
        for (int w = 0; w < 8; w++) { wexcl[w] = s; s += wsum[w]; }
        wexcl[8] = s;
    }
    __syncthreads();
    if (i < n) g_rowptr[i] = wexcl[wid] + x - v;     // block-local exclusive
    if (tid == 0) g_bsum[blockIdx.x] = wexcl[8];
}

// ---------------------------------------------------------------------------
// Fused launch: blocks [0, nb) finish the scan (each block REDUCES the bsum
// of its predecessors — no serial scan-of-sums kernel needed) and reset cnt;
// blocks [nb, nb+gb) run the layer-1 GEMM (independent: needs only degw/x/W1).
// The scan half is 196 tiny blocks that finish in the first wave, so the GEMM
// half is not delayed (unlike the R8 bucket+gemm fusion).
// ---------------------------------------------------------------------------
__global__ void k_scanCG(const float* __restrict__ x,
                         const float* __restrict__ W,
                         int n, int nb) {
    __shared__ float Ws[NF * NF];           // used by gemm half
    __shared__ float xs[8][4][NF];
    int tid = threadIdx.x, lane = tid & 31, wid = tid >> 5;

    if (blockIdx.x < nb) {
        // ---- scan finish: excl = sum(bsum[0..bid-1]) ----
        __shared__ int wred[8];
        int bid = blockIdx.x;
        int v = (tid < bid) ? g_bsum[tid] : 0;   // tid < bid <= nb-1 < 256
#pragma unroll
        for (int off = 16; off >= 1; off >>= 1)
            v += __shfl_xor_sync(0xffffffffu, v, off);
        if (lane == 0) wred[wid] = v;
        __syncthreads();
        if (tid == 0) {
            int s = 0;
#pragma unroll
            for (int w = 0; w < 8; w++) s += wred[w];
            wred[0] = s;
            if (bid == nb - 1) g_rowptr[n] = s + g_bsum[bid];  // total edges
        }
        __syncthreads();
        int excl = wred[0];
        int i = bid * 256 + tid;
        if (i < n) {
            g_rowptr[i] += excl;
            g_cnt[i] = 0;                        // reset bucket cursors
        }
        return;
    }

    // ---- gemm1: g_hs1[i][2l,2l+1] = rsqrt(degw[i]) * (x[i] @ W1)[2l,2l+1] ----
    for (int i = tid; i < NF * NF; i += blockDim.x) Ws[i] = W[i];
    __syncthreads();

    int warp = wid;
    int row0 = ((blockIdx.x - nb) * 8 + warp) * 4;
    if (row0 >= n) return;
    const float2* Ws2 = (const float2*)Ws;

#pragma unroll
    for (int r = 0; r < 4; r++) {
        int row = row0 + r;
        if (row < n) {
            xs[warp][r][lane]      = x[row * NF + lane];
            xs[warp][r][lane + 32] = x[row * NF + lane + 32];
        }
    }
    __syncwarp();

    float acc[4][2] = {};
#pragma unroll
    for (int k = 0; k < NF; k++) {
        float2 wv = Ws2[k * 32 + lane];     // W[k][2l], W[k][2l+1]
#pragma unroll
        for (int r = 0; r < 4; r++) {
            float xv = xs[warp][r][k];
            acc[r][0] = fmaf(xv, wv.x, acc[r][0]);
            acc[r][1] = fmaf(xv, wv.y, acc[r][1]);
        }
    }
#pragma unroll
    for (int r = 0; r < 4; r++) {
        int row = row0 + r;
        if (row < n) {
            float dv = rsqrtf(g_degw[row]);
            g_hs1[row * 32 + lane] =
                __floats2half2_rn(dv * acc[r][0], dv * acc[r][1]);
        }
    }
}

__global__ void k_bucket(const void* __restrict__ ei,
                         const float* __restrict__ ew, int E) {
    int e = blockIdx.x * blockDim.x + threadIdx.x;
    if (e < E) {
        int s = load_idx(ei, e);
        int d = load_idx(ei, (long long)E + e);
        int pos = g_rowptr[d] + atomicAdd(&g_cnt[d], 1);
        int2 p; p.x = s; p.y = __float_as_int(ew[e]);
        g_edge[pos] = p;
    }
}

// ---------------------------------------------------------------------------
// Fused: gather layer 1 -> finalize -> GEMM layer 2 -> scale (fp16 out)
// Persistent grid; warp per node, lane owns features (2l, 2l+1).
// ---------------------------------------------------------------------------
__global__ void k_g1g2(const float* __restrict__ b1,
                       const float* __restrict__ W2, int n) {
    __shared__ float W2s[NF * NF];
    int tid = threadIdx.x;
    for (int i = tid; i < NF * NF; i += blockDim.x) W2s[i] = W2[i];
    __syncthreads();

    int lane = tid & 31;
    int gwarp = (blockIdx.x * blockDim.x + tid) >> 5;
    int nwarps = (gridDim.x * blockDim.x) >> 5;
    float bb0 = b1[2 * lane], bb1 = b1[2 * lane + 1];
    const float2* W2s2 = (const float2*)W2s;

    for (int row = gwarp; row < n; row += nwarps) {
        int beg = g_rowptr[row], end = g_rowptr[row + 1];
        float2 a = __half22float2(g_hs1[row * 32 + lane]);   // self loop (w=1)
        int e = beg;
        for (; e + 7 < end; e += 8) {
            int2 E0 = g_edge[e],   E1 = g_edge[e+1], E2 = g_edge[e+2], E3 = g_edge[e+3];
            int2 E4 = g_edge[e+4], E5 = g_edge[e+5], E6 = g_edge[e+6], E7 = g_edge[e+7];
            float2 v0 = __half22float2(g_hs1[E0.x * 32 + lane]);
            float2 v1 = __half22float2(g_hs1[E1.x * 32 + lane]);
            float2 v2 = __half22float2(g_hs1[E2.x * 32 + lane]);
            float2 v3 = __half22float2(g_hs1[E3.x * 32 + lane]);
            float2 v4 = __half22float2(g_hs1[E4.x * 32 + lane]);
            float2 v5 = __half22float2(g_hs1[E5.x * 32 + lane]);
            float2 v6 = __half22float2(g_hs1[E6.x * 32 + lane]);
            float2 v7 = __half22float2(g_hs1[E7.x * 32 + lane]);
            float w0 = __int_as_float(E0.y), w1 = __int_as_float(E1.y);
            float w2 = __int_as_float(E2.y), w3 = __int_as_float(E3.y);
            float w4 = __int_as_float(E4.y), w5 = __int_as_float(E5.y);
            float w6 = __int_as_float(E6.y), w7 = __int_as_float(E7.y);
            a.x = fmaf(w0, v0.x, a.x);  a.y = fmaf(w0, v0.y, a.y);
            a.x = fmaf(w1, v1.x, a.x);  a.y = fmaf(w1, v1.y, a.y);
            a.x = fmaf(w2, v2.x, a.x);  a.y = fmaf(w2, v2.y, a.y);
            a.x = fmaf(w3, v3.x, a.x);  a.y = fmaf(w3, v3.y, a.y);
            a.x = fmaf(w4, v4.x, a.x);  a.y = fmaf(w4, v4.y, a.y);
            a.x = fmaf(w5, v5.x, a.x);  a.y = fmaf(w5, v5.y, a.y);
            a.x = fmaf(w6, v6.x, a.x);  a.y = fmaf(w6, v6.y, a.y);
            a.x = fmaf(w7, v7.x, a.x);  a.y = fmaf(w7, v7.y, a.y);
        }
        for (; e < end; e++) {
            int2 E0 = g_edge[e];
            float2 v = __half22float2(g_hs1[E0.x * 32 + lane]);
            float w = __int_as_float(E0.y);
            a.x = fmaf(w, v.x, a.x);  a.y = fmaf(w, v.y, a.y);
        }
        float dv = rsqrtf(g_degw[row]);
        float h0 = fmaxf(fmaf(dv, a.x, bb0), 0.f);   // feature 2*lane
        float h1 = fmaxf(fmaf(dv, a.y, bb1), 0.f);   // feature 2*lane+1

        // hs2[row][2l,2l+1] = dv * sum_k h[k] * W2[k][2l,2l+1]
        float acc0 = 0.f, acc1 = 0.f;
#pragma unroll
        for (int kk = 0; kk < 32; kk++) {
            float hk0 = __shfl_sync(0xffffffffu, h0, kk);   // feature 2kk
            float hk1 = __shfl_sync(0xffffffffu, h1, kk);   // feature 2kk+1
            float2 wr0 = W2s2[(2 * kk) * 32 + lane];
            float2 wr1 = W2s2[(2 * kk + 1) * 32 + lane];
            acc0 = fmaf(hk0, wr0.x, acc0);  acc1 = fmaf(hk0, wr0.y, acc1);
            acc0 = fmaf(hk1, wr1.x, acc0);  acc1 = fmaf(hk1, wr1.y, acc1);
        }
        g_hs2[row * 32 + lane] = __floats2half2_rn(dv * acc0, dv * acc1);
    }
}

// ---------------------------------------------------------------------------
// Fused: gather layer 2 -> finalize -> FC head
// ---------------------------------------------------------------------------
__global__ void k_g2fc(const float* __restrict__ b2,
                       const float* __restrict__ Wfc,
                       const float* __restrict__ bfc,
                       float* __restrict__ out, int n) {
    int tid = threadIdx.x;
    int lane = tid & 31;
    int gwarp = (blockIdx.x * blockDim.x + tid) >> 5;
    int nwarps = (gridDim.x * blockDim.x) >> 5;

    float bb0 = b2[2 * lane], bb1 = b2[2 * lane + 1];
    float wf0[OUTF], wf1[OUTF];
#pragma unroll
    for (int j = 0; j < OUTF; j++) {
        wf0[j] = Wfc[(2 * lane) * OUTF + j];
        wf1[j] = Wfc[(2 * lane + 1) * OUTF + j];
    }
    float bfs = (lane < OUTF) ? bfc[lane] : 0.f;

    for (int row = gwarp; row < n; row += nwarps) {
        int beg = g_rowptr[row], end = g_rowptr[row + 1];
        float2 a = __half22float2(g_hs2[row * 32 + lane]);   // self loop
        int e = beg;
        for (; e + 7 < end; e += 8) {
            int2 E0 = g_edge[e],   E1 = g_edge[e+1], E2 = g_edge[e+2], E3 = g_edge[e+3];
            int2 E4 = g_edge[e+4], E5 = g_edge[e+5], E6 = g_edge[e+6], E7 = g_edge[e+7];
            float2 v0 = __half22float2(g_hs2[E0.x * 32 + lane]);
            float2 v1 = __half22float2(g_hs2[E1.x * 32 + lane]);
            float2 v2 = __half22float2(g_hs2[E2.x * 32 + lane]);
            float2 v3 = __half22float2(g_hs2[E3.x * 32 + lane]);
            float2 v4 = __half22float2(g_hs2[E4.x * 32 + lane]);
            float2 v5 = __half22float2(g_hs2[E5.x * 32 + lane]);
            float2 v6 = __half22float2(g_hs2[E6.x * 32 + lane]);
            float2 v7 = __half22float2(g_hs2[E7.x * 32 + lane]);
            float w0 = __int_as_float(E0.y), w1 = __int_as_float(E1.y);
            float w2 = __int_as_float(E2.y), w3 = __int_as_float(E3.y);
            float w4 = __int_as_float(E4.y), w5 = __int_as_float(E5.y);
            float w6 = __int_as_float(E6.y), w7 = __int_as_float(E7.y);
            a.x = fmaf(w0, v0.x, a.x);  a.y = fmaf(w0, v0.y, a.y);
            a.x = fmaf(w1, v1.x, a.x);  a.y = fmaf(w1, v1.y, a.y);
            a.x = fmaf(w2, v2.x, a.x);  a.y = fmaf(w2, v2.y, a.y);
            a.x = fmaf(w3, v3.x, a.x);  a.y = fmaf(w3, v3.y, a.y);
            a.x = fmaf(w4, v4.x, a.x);  a.y = fmaf(w4, v4.y, a.y);
            a.x = fmaf(w5, v5.x, a.x);  a.y = fmaf(w5, v5.y, a.y);
            a.x = fmaf(w6, v6.x, a.x);  a.y = fmaf(w6, v6.y, a.y);
            a.x = fmaf(w7, v7.x, a.x);  a.y = fmaf(w7, v7.y, a.y);
        }
        for (; e < end; e++) {
            int2 E0 = g_edge[e];
            float2 v = __half22float2(g_hs2[E0.x * 32 + lane]);
            float w = __int_as_float(E0.y);
            a.x = fmaf(w, v.x, a.x);  a.y = fmaf(w, v.y, a.y);
        }
        float dv = rsqrtf(g_degw[row]);
        float h0 = fmaxf(fmaf(dv, a.x, bb0), 0.f);
        float h1 = fmaxf(fmaf(dv, a.y, bb1), 0.f);

        float p[OUTF];
#pragma unroll
        for (int j = 0; j < OUTF; j++)
            p[j] = fmaf(h0, wf0[j], h1 * wf1[j]);
#pragma unroll
        for (int off = 16; off >= 1; off >>= 1)
#pragma unroll
            for (int j = 0; j < OUTF; j++)
                p[j] += __shfl_xor_sync(0xffffffffu, p[j], off);
        if (lane < OUTF)
            out[row * OUTF + lane] = p[lane] + bfs;  // all lanes hold full sums
    }
}

// ---------------------------------------------------------------------------
extern "C" void kernel_launch(void* const* d_in, const int* in_sizes, int n_in,
                              void* d_out, int out_size) {
    const float* x   = (const float*)d_in[0];
    const void*  ei  = d_in[1];                      // int32 OR int64 [2, E]
    const float* ea  = (const float*)d_in[2];        // [E, 1]
    const float* W1  = (const float*)d_in[3];
    const float* b1  = (const float*)d_in[4];
    const float* W2  = (const float*)d_in[5];
    const float* b2  = (const float*)d_in[6];
    const float* Wfc = (const float*)d_in[7];
    const float* bfc = (const float*)d_in[8];
    float* out = (float*)d_out;

    int N = in_sizes[0] / NF;
    int E = in_sizes[1] / 2;

    int nb = (N + 255) / 256;                        // scan blocks (<=256)
    int eb = (E + 255) / 256;
    int gb = (N + 31) / 32;                          // gemm1: 32 rows / block
    int pg = 148 * 8;                                // persistent gather grid
    int need = (N + 7) / 8;
    if (pg > need) pg = need;

    // CSR build (shared by both layers); gemm1 overlapped with scan finish
    k_init  <<<nb, 256>>>((const unsigned int*)ei, N);
    k_count <<<eb, 256>>>(ei, ea, E);
    k_scanA <<<nb, 256>>>(N);
    k_scanCG<<<nb + gb, 256>>>(x, W1, N, nb);
    k_bucket<<<eb, 256>>>(ei, ea, E);

    // Fused gather1+GEMM2, then fused gather2+FC
    k_g1g2<<<pg, 256>>>(b1, W2, N);
    k_g2fc<<<pg, 256>>>(b2, Wfc, bfc, out, N);
}